// round 4
// baseline (speedup 1.0000x reference)
#include <cuda_runtime.h>
#include <cuda_bf16.h>
#include <math.h>

// Problem constants
#define BB 64
#define TT 128
#define TS 127          // timesteps = T-1
#define VV 10000
#define EE 300
#define HH 1024
#define G4 4096         // 4*H
#define KT 16           // k-tile depth

typedef unsigned long long u64;

// ---------------- scratch (static device memory; no allocations) -------------
__device__ float g_pre0[(size_t)TS * BB * G4];     // x@w_ih0 + b0, row = t*64+b
__device__ float g_h1all[(size_t)TS * BB * HH];    // all layer-1 hidden states
__device__ float g_h0buf[2][BB * HH];
__device__ float g_c0[BB * HH];
__device__ float g_c1[BB * HH];
__device__ float g_rowloss[TS * BB];

__device__ __forceinline__ float sigmoidf_(float x) {
    return 1.0f / (1.0f + expf(-x));
}
__device__ __forceinline__ u64 fma2_(u64 a, u64 b, u64 c) {
    u64 d; asm("fma.rn.f32x2 %0, %1, %2, %3;" : "=l"(d) : "l"(a), "l"(b), "l"(c));
    return d;
}
__device__ __forceinline__ u64 pack2_(float x) {
    u64 d; asm("mov.b64 %0, {%1, %1};" : "=l"(d) : "f"(x));
    return d;
}
__device__ __forceinline__ float2 unpack2_(u64 a) {
    float2 f; asm("mov.b64 {%0, %1}, %2;" : "=f"(f.x), "=f"(f.y) : "l"(a));
    return f;
}

// ---------------- init: zero recurrent state every replay --------------------
__global__ void init_state_kernel() {
    int i = blockIdx.x * blockDim.x + threadIdx.x;
    if (i < BB * HH) { g_h0buf[0][i] = 0.f; g_c0[i] = 0.f; g_c1[i] = 0.f; }
}

// ---------------- pre0 = gather(emb) @ w_ih0 + b0 ----------------------------
__global__ __launch_bounds__(256) void pre0_gemm_kernel(
    const int* __restrict__ sent, const float* __restrict__ wordvec,
    const float* __restrict__ w_ih0, const float* __restrict__ b0)
{
    __shared__ float As[4][64];
    __shared__ float Bs[4][64];
    const int t = blockIdx.y;
    const int colBase = blockIdx.x * 64;
    const int tid = threadIdx.x;
    const int tx = tid & 15, ty = tid >> 4;

    const float* arow = nullptr;
    if (tid < 64) {
        int token = sent[tid * TT + t];
        arow = wordvec + (size_t)token * EE;
    }
    const int bRow = tid >> 6, bCol = tid & 63;

    float acc[4][4] = {};
    for (int kt = 0; kt < 75; kt++) {
        __syncthreads();
        if (tid < 64) {
            float4 a = *(const float4*)(arow + kt * 4);
            As[0][tid] = a.x; As[1][tid] = a.y; As[2][tid] = a.z; As[3][tid] = a.w;
        }
        Bs[bRow][bCol] = w_ih0[(size_t)(kt * 4 + bRow) * G4 + colBase + bCol];
        __syncthreads();
#pragma unroll
        for (int k = 0; k < 4; k++) {
            float4 a4 = *(const float4*)&As[k][ty * 4];
            float4 b4 = *(const float4*)&Bs[k][tx * 4];
            acc[0][0] += a4.x * b4.x; acc[0][1] += a4.x * b4.y; acc[0][2] += a4.x * b4.z; acc[0][3] += a4.x * b4.w;
            acc[1][0] += a4.y * b4.x; acc[1][1] += a4.y * b4.y; acc[1][2] += a4.y * b4.z; acc[1][3] += a4.y * b4.w;
            acc[2][0] += a4.z * b4.x; acc[2][1] += a4.z * b4.y; acc[2][2] += a4.z * b4.z; acc[2][3] += a4.z * b4.w;
            acc[3][0] += a4.w * b4.x; acc[3][1] += a4.w * b4.y; acc[3][2] += a4.w * b4.z; acc[3][3] += a4.w * b4.w;
        }
    }
    float* dst = g_pre0 + ((size_t)t * 64) * G4 + colBase;
#pragma unroll
    for (int i = 0; i < 4; i++) {
        int b_ = ty * 4 + i;
#pragma unroll
        for (int j = 0; j < 4; j++) {
            int c = tx * 4 + j;
            dst[(size_t)b_ * G4 + c] = acc[i][j] + b0[colBase + c];
        }
    }
}

// ---------------- LSTM step: one launch per s ---------------------------------
// CTAs [0,64):  layer0 step t=s   (valid s<=126): h0[s] @ w_hh0, K=1024
// CTAs [64,128): layer1 step t=s-1 (valid s>=1):  [h0(t); h1(t-1)] @ [w_ih1; w_hh1], K<=2048
// Each CTA: 64 rows x 64 gate-cols (16 j x 4 gates), 256 threads, 4x4 f32x2 tiles.
__global__ __launch_bounds__(256) void step2_kernel(
    int s, const float* __restrict__ w_hh0, const float* __restrict__ w_ih1,
    const float* __restrict__ w_hh1, const float* __restrict__ b1)
{
    const bool isL0 = blockIdx.x < 64;
    if (isL0 && s >= TS) return;
    if (!isL0 && s < 1) return;
    const int t = isL0 ? s : s - 1;
    const int cb = blockIdx.x & 63;
    const int j0 = cb * 16;

    __shared__ __align__(16) float hs[2][KT][64];
    __shared__ __align__(16) float ws[2][KT][64];
    __shared__ float gbuf[64][65];

    const int tid = threadIdx.x;
    // loader indices
    const int hr = tid & 63, hk4 = tid >> 6;            // h: row, k-quad
    const int wc4 = tid & 15, wk = tid >> 4;            // w: col-quad, k-row
    const int wgate = wc4 >> 2, wjb = (wc4 & 3) * 4;
    // compute indices
    const int rg = tid & 15, cg = tid >> 4;
    const int r0 = rg * 4, c0 = cg * 4;

    // segment sources
    const float* hA; const float* WA; const float* hB = nullptr; const float* WB = nullptr;
    if (isL0) { hA = g_h0buf[s & 1]; WA = w_hh0; }
    else {
        hA = g_h0buf[s & 1]; WA = w_ih1;
        if (t > 0) { hB = g_h1all + (size_t)(t - 1) * BB * HH; WB = w_hh1; }
    }
    const int nt = hB ? 128 : 64;

    float4 hv, wv;
    {   // prologue tile 0
        hv = *(const float4*)&hA[hr * HH + hk4 * 4];
        wv = *(const float4*)&WA[(size_t)wk * G4 + wgate * HH + j0 + wjb];
        hs[0][hk4 * 4 + 0][hr] = hv.x;
        hs[0][hk4 * 4 + 1][hr] = hv.y;
        hs[0][hk4 * 4 + 2][hr] = hv.z;
        hs[0][hk4 * 4 + 3][hr] = hv.w;
        *(float4*)&ws[0][wk][wc4 * 4] = wv;
    }

    u64 acc[2][4] = {};
    for (int tl = 0; tl < nt; tl++) {
        __syncthreads();
        const int cur = tl & 1;
        float4 nh, nw;
        if (tl + 1 < nt) {
            const int nxt = tl + 1;
            const float* h = (nxt < 64) ? hA : hB;
            const float* W = (nxt < 64) ? WA : WB;
            const int k0 = (nxt & 63) * KT;
            nh = *(const float4*)&h[hr * HH + k0 + hk4 * 4];
            nw = *(const float4*)&W[(size_t)(k0 + wk) * G4 + wgate * HH + j0 + wjb];
        }
#pragma unroll
        for (int k = 0; k < KT; k++) {
            ulonglong2 hp = *(const ulonglong2*)&hs[cur][k][r0];
            float4 w4 = *(const float4*)&ws[cur][k][c0];
            u64 w0 = pack2_(w4.x), w1 = pack2_(w4.y);
            u64 w2 = pack2_(w4.z), w3 = pack2_(w4.w);
            acc[0][0] = fma2_(hp.x, w0, acc[0][0]);
            acc[0][1] = fma2_(hp.x, w1, acc[0][1]);
            acc[0][2] = fma2_(hp.x, w2, acc[0][2]);
            acc[0][3] = fma2_(hp.x, w3, acc[0][3]);
            acc[1][0] = fma2_(hp.y, w0, acc[1][0]);
            acc[1][1] = fma2_(hp.y, w1, acc[1][1]);
            acc[1][2] = fma2_(hp.y, w2, acc[1][2]);
            acc[1][3] = fma2_(hp.y, w3, acc[1][3]);
        }
        if (tl + 1 < nt) {
            const int nb = cur ^ 1;
            hs[nb][hk4 * 4 + 0][hr] = nh.x;
            hs[nb][hk4 * 4 + 1][hr] = nh.y;
            hs[nb][hk4 * 4 + 2][hr] = nh.z;
            hs[nb][hk4 * 4 + 3][hr] = nh.w;
            *(float4*)&ws[nb][wk][wc4 * 4] = nw;
        }
    }

    // gates -> smem for per-j regrouping
#pragma unroll
    for (int rp = 0; rp < 2; rp++) {
#pragma unroll
        for (int c = 0; c < 4; c++) {
            float2 v = unpack2_(acc[rp][c]);
            gbuf[r0 + rp * 2 + 0][c0 + c] = v.x;
            gbuf[r0 + rp * 2 + 1][c0 + c] = v.y;
        }
    }
    __syncthreads();

    // pointwise: thread handles 4 (r, j) items
    const int r = tid & 63;
    const int jlb = (tid >> 6) * 4;
    if (isL0) {
        const float* av = g_pre0 + ((size_t)t * BB + r) * G4;
        float* hout = g_h0buf[(s + 1) & 1];
#pragma unroll
        for (int i = 0; i < 4; i++) {
            int jl = jlb + i, j = j0 + jl;
            float gi = gbuf[r][jl]      + av[j];
            float gf = gbuf[r][16 + jl] + av[HH + j];
            float gg = gbuf[r][32 + jl] + av[2 * HH + j];
            float go = gbuf[r][48 + jl] + av[3 * HH + j];
            float c  = g_c0[r * HH + j];
            float cn = sigmoidf_(gf) * c + sigmoidf_(gi) * tanhf(gg);
            float hn = sigmoidf_(go) * tanhf(cn);
            g_c0[r * HH + j] = cn;
            hout[r * HH + j] = hn;
        }
    } else {
        float* hout = g_h1all + (size_t)t * BB * HH;
#pragma unroll
        for (int i = 0; i < 4; i++) {
            int jl = jlb + i, j = j0 + jl;
            float gi = gbuf[r][jl]      + b1[j];
            float gf = gbuf[r][16 + jl] + b1[HH + j];
            float gg = gbuf[r][32 + jl] + b1[2 * HH + j];
            float go = gbuf[r][48 + jl] + b1[3 * HH + j];
            float c  = g_c1[r * HH + j];
            float cn = sigmoidf_(gf) * c + sigmoidf_(gi) * tanhf(gg);
            float hn = sigmoidf_(go) * tanhf(cn);
            g_c1[r * HH + j] = cn;
            hout[r * HH + j] = hn;
        }
    }
}

// ---------------- logits = h1all @ w_out + b_out (f32x2 4x4) ------------------
// grid (157, 127): CTA = 64 rows (batch at fixed t) x 64 vocab cols.
// NOTE: temp = out + 1 is only 4-byte aligned -> all stores to temp are scalar.
__global__ __launch_bounds__(256) void logits2_kernel(
    const float* __restrict__ w_out, const float* __restrict__ b_out,
    float* __restrict__ temp)
{
    __shared__ __align__(16) float As[2][KT][64];
    __shared__ __align__(16) float Bs[2][KT][64];
    const int t = blockIdx.y;
    const int colBase = blockIdx.x * 64;
    const int tid = threadIdx.x;

    const int ar = tid & 63, ak4 = tid >> 6;
    const int bc4 = tid & 15, bk = tid >> 4;
    const int rg = tid & 15, cg = tid >> 4;
    const int r0 = rg * 4, c0 = cg * 4;

    const float* Abase = g_h1all + (size_t)t * BB * HH;
    const int bcol = colBase + bc4 * 4;
    const bool bok = (bcol + 3 < VV);

    auto loadB = [&](int k0, float4& v) {
        const float* p = w_out + (size_t)(k0 + bk) * VV + bcol;
        if (bok) v = *(const float4*)p;
        else {
            v.x = (bcol + 0 < VV) ? p[0] : 0.f;
            v.y = (bcol + 1 < VV) ? p[1] : 0.f;
            v.z = (bcol + 2 < VV) ? p[2] : 0.f;
            v.w = (bcol + 3 < VV) ? p[3] : 0.f;
        }
    };

    float4 av, bv;
    av = *(const float4*)&Abase[ar * HH + ak4 * 4];
    loadB(0, bv);
    As[0][ak4 * 4 + 0][ar] = av.x;
    As[0][ak4 * 4 + 1][ar] = av.y;
    As[0][ak4 * 4 + 2][ar] = av.z;
    As[0][ak4 * 4 + 3][ar] = av.w;
    *(float4*)&Bs[0][bk][bc4 * 4] = bv;

    u64 acc[2][4] = {};
    for (int tl = 0; tl < 64; tl++) {
        __syncthreads();
        const int cur = tl & 1;
        float4 na, nb;
        if (tl + 1 < 64) {
            const int k0 = (tl + 1) * KT;
            na = *(const float4*)&Abase[ar * HH + k0 + ak4 * 4];
            loadB(k0, nb);
        }
#pragma unroll
        for (int k = 0; k < KT; k++) {
            ulonglong2 hp = *(const ulonglong2*)&As[cur][k][r0];
            float4 w4 = *(const float4*)&Bs[cur][k][c0];
            u64 w0 = pack2_(w4.x), w1 = pack2_(w4.y);
            u64 w2 = pack2_(w4.z), w3 = pack2_(w4.w);
            acc[0][0] = fma2_(hp.x, w0, acc[0][0]);
            acc[0][1] = fma2_(hp.x, w1, acc[0][1]);
            acc[0][2] = fma2_(hp.x, w2, acc[0][2]);
            acc[0][3] = fma2_(hp.x, w3, acc[0][3]);
            acc[1][0] = fma2_(hp.y, w0, acc[1][0]);
            acc[1][1] = fma2_(hp.y, w1, acc[1][1]);
            acc[1][2] = fma2_(hp.y, w2, acc[1][2]);
            acc[1][3] = fma2_(hp.y, w3, acc[1][3]);
        }
        if (tl + 1 < 64) {
            const int nbuf = cur ^ 1;
            As[nbuf][ak4 * 4 + 0][ar] = na.x;
            As[nbuf][ak4 * 4 + 1][ar] = na.y;
            As[nbuf][ak4 * 4 + 2][ar] = na.z;
            As[nbuf][ak4 * 4 + 3][ar] = na.w;
            *(float4*)&Bs[nbuf][bk][bc4 * 4] = nb;
        }
    }

    const int colT = colBase + c0;
    float bias[4];
#pragma unroll
    for (int c = 0; c < 4; c++)
        bias[c] = (colT + c < VV) ? b_out[colT + c] : 0.f;

#pragma unroll
    for (int rr = 0; rr < 4; rr++) {
        const int b_ = r0 + rr;
        float2 v0 = unpack2_(acc[rr >> 1][0]);
        float2 v1 = unpack2_(acc[rr >> 1][1]);
        float2 v2 = unpack2_(acc[rr >> 1][2]);
        float2 v3 = unpack2_(acc[rr >> 1][3]);
        float o[4];
        if (rr & 1) { o[0] = v0.y; o[1] = v1.y; o[2] = v2.y; o[3] = v3.y; }
        else        { o[0] = v0.x; o[1] = v1.x; o[2] = v2.x; o[3] = v3.x; }
        float* dst = temp + ((size_t)b_ * TS + t) * VV + colT;
#pragma unroll
        for (int c = 0; c < 4; c++) {
            if (colT + c < VV) dst[c] = o[c] + bias[c];   // scalar: temp is 4B-aligned
        }
    }
}

// ---------------- loss: per-row -logp/length (deterministic) -----------------
__global__ __launch_bounds__(256) void loss_row_kernel(
    const float* __restrict__ temp, const int* __restrict__ sent,
    const int* __restrict__ length)
{
    __shared__ float sm[256];
    __shared__ float ss[256];
    const int row = blockIdx.x;            // b*127 + t
    const int b = row / TS, t = row % TS;
    const float* x = temp + (size_t)row * VV;
    const int tid = threadIdx.x;

    float m = -1e30f, s = 0.f;
    for (int i = tid; i < VV; i += 256) {
        float v = x[i];
        float M = fmaxf(m, v);
        s = s * expf(m - M) + expf(v - M);
        m = M;
    }
    sm[tid] = m; ss[tid] = s;
    __syncthreads();
    for (int w = 128; w > 0; w >>= 1) {
        if (tid < w) {
            float m2 = sm[tid + w], s2 = ss[tid + w];
            float M = fmaxf(sm[tid], m2);
            ss[tid] = ss[tid] * expf(sm[tid] - M) + s2 * expf(m2 - M);
            sm[tid] = M;
        }
        __syncthreads();
    }
    if (tid == 0) {
        int gt = sent[b * TT + t + 1];
        float lse = sm[0] + logf(ss[0]);
        float res = 0.f;
        if (gt != 0) {
            float lp = x[gt] - lse;
            res = -lp / (float)length[b];
        }
        g_rowloss[row] = res;
    }
}

__global__ __launch_bounds__(256) void loss_final_kernel(float* __restrict__ out) {
    __shared__ float s[256];
    const int tid = threadIdx.x;
    float a = 0.f;
    for (int i = tid; i < TS * BB; i += 256) a += g_rowloss[i];
    s[tid] = a;
    __syncthreads();
    for (int w = 128; w > 0; w >>= 1) {
        if (tid < w) s[tid] += s[tid + w];
        __syncthreads();
    }
    if (tid == 0) out[0] = s[0];
}

// ---------------- host launcher ----------------------------------------------
extern "C" void kernel_launch(void* const* d_in, const int* in_sizes, int n_in,
                              void* d_out, int out_size)
{
    const int*   sent    = (const int*)d_in[0];
    const int*   length  = (const int*)d_in[1];
    const float* wordvec = (const float*)d_in[2];
    const float* w_ih0   = (const float*)d_in[3];
    const float* w_hh0   = (const float*)d_in[4];
    const float* b0      = (const float*)d_in[5];
    const float* w_ih1   = (const float*)d_in[6];
    const float* w_hh1   = (const float*)d_in[7];
    const float* b1      = (const float*)d_in[8];
    const float* w_out   = (const float*)d_in[9];
    const float* b_out   = (const float*)d_in[10];
    float* out = (float*)d_out;

    const long long TEMP_N = (long long)BB * TS * VV;
    int off = ((long long)out_size > TEMP_N) ? (int)((long long)out_size - TEMP_N) : 0;
    float* temp = out + off;

    init_state_kernel<<<256, 256>>>();
    pre0_gemm_kernel<<<dim3(64, TS), 256>>>(sent, wordvec, w_ih0, b0);
    for (int s = 0; s <= TS; s++) {
        step2_kernel<<<128, 256>>>(s, w_hh0, w_ih1, w_hh1, b1);
    }
    logits2_kernel<<<dim3(157, TS), 256>>>(w_out, b_out, temp);
    if (off > 0) {
        loss_row_kernel<<<TS * BB, 256>>>(temp, sent, length);
        loss_final_kernel<<<1, 256>>>(out);
    }
}